// round 1
// baseline (speedup 1.0000x reference)
#include <cuda_runtime.h>
#include <cstdint>
#include <cstddef>

// Problem constants (fixed by setup_inputs)
#define BATCH 4
#define SEQ   1024
#define DIM   1152
#define HEADS 16
#define HDIM  72
#define ROWS  (BATCH*SEQ)          // 4096
#define QKVN  (3*DIM)              // 3456
#define TOTAL_ELEMS 4718592.0f     // B*H*N*hd for loss mean

// Scratch (static device allocation — allowed)
__device__ __align__(16) float g_qkv [(size_t)ROWS * QKVN];   // 56.6 MB, (B*N, 3456)
__device__ __align__(16) float g_xout[(size_t)ROWS * DIM];    // 18.9 MB, (B*N, 1152) = (B,N,H,hd)

// ---------------------------------------------------------------------------
// GEMM: C[m,n] = sum_k A[m,k] * W[n,k] + bias[n]
// BM=128, BN=64, BK=16, 256 threads, 8x4 micro-tile
// ---------------------------------------------------------------------------
__global__ __launch_bounds__(256)
void gemm_bias_kernel(const float* __restrict__ A, const float* __restrict__ W,
                      const float* __restrict__ bias, float* __restrict__ C,
                      int M, int N, int K)
{
    __shared__ __align__(16) float As[16][128];
    __shared__ __align__(16) float Bs[16][64];

    const int tid = threadIdx.x;
    const int tx = tid & 15;         // 0..15 -> n
    const int ty = tid >> 4;         // 0..15 -> m
    const int m0 = blockIdx.y * 128;
    const int n0 = blockIdx.x * 64;

    float acc[8][4];
#pragma unroll
    for (int i = 0; i < 8; i++)
#pragma unroll
        for (int j = 0; j < 4; j++) acc[i][j] = 0.f;

    const int ktiles = K >> 4;
    for (int kt = 0; kt < ktiles; kt++) {
        const int k0 = kt << 4;
        // Load A tile: 128 rows x 16 cols = 512 float4
#pragma unroll
        for (int r = 0; r < 2; r++) {
            int e = tid + r * 256;
            int row = e >> 2;
            int kc  = (e & 3) << 2;
            float4 va = *(const float4*)&A[(size_t)(m0 + row) * K + k0 + kc];
            As[kc + 0][row] = va.x; As[kc + 1][row] = va.y;
            As[kc + 2][row] = va.z; As[kc + 3][row] = va.w;
        }
        // Load B tile: 64 rows x 16 cols = 256 float4
        {
            int row = tid >> 2;
            int kc  = (tid & 3) << 2;
            float4 vb = *(const float4*)&W[(size_t)(n0 + row) * K + k0 + kc];
            Bs[kc + 0][row] = vb.x; Bs[kc + 1][row] = vb.y;
            Bs[kc + 2][row] = vb.z; Bs[kc + 3][row] = vb.w;
        }
        __syncthreads();
#pragma unroll
        for (int k = 0; k < 16; k++) {
            float4 a0 = *(const float4*)&As[k][ty * 8];
            float4 a1 = *(const float4*)&As[k][ty * 8 + 4];
            float4 b  = *(const float4*)&Bs[k][tx * 4];
            float am[8] = {a0.x, a0.y, a0.z, a0.w, a1.x, a1.y, a1.z, a1.w};
            float bn[4] = {b.x, b.y, b.z, b.w};
#pragma unroll
            for (int i = 0; i < 8; i++)
#pragma unroll
                for (int j = 0; j < 4; j++) acc[i][j] += am[i] * bn[j];
        }
        __syncthreads();
    }

    const float4 bv = *(const float4*)&bias[n0 + tx * 4];
#pragma unroll
    for (int i = 0; i < 8; i++) {
        float4 o;
        o.x = acc[i][0] + bv.x; o.y = acc[i][1] + bv.y;
        o.z = acc[i][2] + bv.z; o.w = acc[i][3] + bv.w;
        *(float4*)&C[(size_t)(m0 + ty * 8 + i) * N + n0 + tx * 4] = o;
    }
}

// ---------------------------------------------------------------------------
// Fused dual attention + distill loss.
// grid: (16 q-tiles, 64 bh). block: 256 threads = 8 warps.
// Each warp owns 8 queries; 4 lanes per query, each lane owns 18 dims.
// Pass 0: own K/V (from g_qkv) -> writes g_xout. Pass 1: encoder K/V -> loss.
// ---------------------------------------------------------------------------
__global__ __launch_bounds__(256)
void attn_kernel(const float* __restrict__ enc_k, const float* __restrict__ enc_v,
                 float* __restrict__ loss_out)
{
    __shared__ __align__(16) float Ks[64][72];
    __shared__ __align__(16) float Vs[64][72];

    const int tid  = threadIdx.x;
    const int lane = tid & 31;
    const int warp = tid >> 5;
    const int sub  = lane & 3;                 // 4 lanes per query
    const int qloc = warp * 8 + (lane >> 2);   // 0..63
    const int bh = blockIdx.y;
    const int b  = bh >> 4;
    const int h  = bh & 15;
    const int n  = blockIdx.x * 64 + qloc;
    const float scale = rsqrtf((float)HDIM);

    // Load this lane's 18 Q dims (pre-scaled)
    float2 qr[9];
    {
        const float* qs = g_qkv + ((size_t)(b * SEQ + n)) * QKVN + h * HDIM + sub * 18;
#pragma unroll
        for (int j = 0; j < 9; j++) {
            float2 v = ((const float2*)qs)[j];
            qr[j].x = v.x * scale; qr[j].y = v.y * scale;
        }
    }

    float xo[18];           // pass-0 output, kept for loss
    float lsum = 0.f;

    for (int p = 0; p < 2; p++) {
        float m = -1e30f, l = 0.f;
        float2 O[9];
#pragma unroll
        for (int j = 0; j < 9; j++) O[j] = make_float2(0.f, 0.f);

        for (int kt = 0; kt < 16; kt++) {
            float2* ksm = (float2*)&Ks[0][0];
            float2* vsm = (float2*)&Vs[0][0];
            if (p == 0) {
#pragma unroll
                for (int r = 0; r < 9; r++) {
                    int e = tid + r * 256;            // 0..2303 (float2 units)
                    int key = e / 36;
                    int dp  = e - key * 36;
                    size_t base = ((size_t)(b * SEQ + kt * 64 + key)) * QKVN + h * HDIM + dp * 2;
                    ksm[e] = *(const float2*)(g_qkv + base + DIM);
                    vsm[e] = *(const float2*)(g_qkv + base + 2 * DIM);
                }
            } else {
                const float2* kst = (const float2*)(enc_k + ((size_t)bh * SEQ + kt * 64) * HDIM);
                const float2* vst = (const float2*)(enc_v + ((size_t)bh * SEQ + kt * 64) * HDIM);
#pragma unroll
                for (int r = 0; r < 9; r++) {
                    int e = tid + r * 256;
                    ksm[e] = kst[e];
                    vsm[e] = vst[e];
                }
            }
            __syncthreads();

            // Scores for 64 keys; each lane keeps 16 of them (static indices)
            float sc[16];
            float tmax = -1e30f;
#pragma unroll
            for (int i = 0; i < 16; i++) {
#pragma unroll
                for (int u = 0; u < 4; u++) {
                    const int kk = i * 4 + u;
                    const float2* kr = (const float2*)&Ks[kk][sub * 18];
                    float s = 0.f;
#pragma unroll
                    for (int j = 0; j < 9; j++) {
                        float2 kv = kr[j];
                        s += qr[j].x * kv.x + qr[j].y * kv.y;
                    }
                    s += __shfl_xor_sync(0xffffffffu, s, 1);
                    s += __shfl_xor_sync(0xffffffffu, s, 2);   // full dot on all 4 lanes
                    if (u == sub) sc[i] = s;
                    tmax = fmaxf(tmax, s);
                }
            }
            // Online softmax update
            float nm = fmaxf(m, tmax);
            float corr = __expf(m - nm);
            l *= corr;
#pragma unroll
            for (int j = 0; j < 9; j++) { O[j].x *= corr; O[j].y *= corr; }
            float ps = 0.f;
#pragma unroll
            for (int i = 0; i < 16; i++) { sc[i] = __expf(sc[i] - nm); ps += sc[i]; }
            ps += __shfl_xor_sync(0xffffffffu, ps, 1);
            ps += __shfl_xor_sync(0xffffffffu, ps, 2);
            l += ps; m = nm;

            // O += P @ V
#pragma unroll
            for (int i = 0; i < 16; i++) {
#pragma unroll
                for (int u = 0; u < 4; u++) {
                    const int kk = i * 4 + u;
                    float pv = __shfl_sync(0xffffffffu, sc[i], (lane & ~3) | u);
                    const float2* vr = (const float2*)&Vs[kk][sub * 18];
#pragma unroll
                    for (int j = 0; j < 9; j++) {
                        float2 vv = vr[j];
                        O[j].x += pv * vv.x; O[j].y += pv * vv.y;
                    }
                }
            }
            __syncthreads();
        }

        const float inv_l = 1.0f / l;
        if (p == 0) {
            float* dst = g_xout + ((size_t)(b * SEQ + n)) * DIM + h * HDIM + sub * 18;
#pragma unroll
            for (int j = 0; j < 9; j++) {
                xo[2 * j]     = O[j].x * inv_l;
                xo[2 * j + 1] = O[j].y * inv_l;
                ((float2*)dst)[j] = make_float2(xo[2 * j], xo[2 * j + 1]);
            }
        } else {
#pragma unroll
            for (int j = 0; j < 9; j++) {
                float d0 = xo[2 * j]     - O[j].x * inv_l;
                float d1 = xo[2 * j + 1] - O[j].y * inv_l;
                lsum += d0 * d0 + d1 * d1;
            }
        }
    }

    // Loss: mean over all elements; warp-reduce then one atomic per warp
    lsum *= (1.0f / TOTAL_ELEMS);
#pragma unroll
    for (int o = 16; o > 0; o >>= 1)
        lsum += __shfl_down_sync(0xffffffffu, lsum, o);
    if (lane == 0) atomicAdd(loss_out, lsum);
}

// ---------------------------------------------------------------------------
extern "C" void kernel_launch(void* const* d_in, const int* in_sizes, int n_in,
                              void* d_out, int out_size)
{
    const float* x      = (const float*)d_in[0];
    const float* enc_k  = (const float*)d_in[1];
    const float* enc_v  = (const float*)d_in[2];
    const float* qkv_w  = (const float*)d_in[3];
    const float* qkv_b  = (const float*)d_in[4];
    const float* proj_w = (const float*)d_in[5];
    const float* proj_b = (const float*)d_in[6];
    float* out = (float*)d_out;
    float* loss_ptr = out + (out_size - 1);

    float* qkv_ptr = nullptr;
    float* xout_ptr = nullptr;
    cudaGetSymbolAddress((void**)&qkv_ptr,  g_qkv);
    cudaGetSymbolAddress((void**)&xout_ptr, g_xout);

    cudaMemsetAsync(loss_ptr, 0, sizeof(float));

    // 1) QKV GEMM: (4096,1152) @ (3456,1152)^T + b -> g_qkv (4096,3456)
    gemm_bias_kernel<<<dim3(QKVN / 64, ROWS / 128), 256>>>(
        x, qkv_w, qkv_b, qkv_ptr, ROWS, QKVN, DIM);

    // 2) Dual attention + loss -> g_xout (4096,1152), loss scalar
    attn_kernel<<<dim3(SEQ / 64, BATCH * HEADS), 256>>>(enc_k, enc_v, loss_ptr);

    // 3) Proj GEMM: (4096,1152) @ (1152,1152)^T + b -> out
    gemm_bias_kernel<<<dim3(DIM / 64, ROWS / 128), 256>>>(
        xout_ptr, proj_w, proj_b, out, ROWS, DIM, DIM);
}

// round 2
// speedup vs baseline: 1.0572x; 1.0572x over previous
#include <cuda_runtime.h>
#include <cstdint>
#include <cstddef>

// Problem constants (fixed by setup_inputs)
#define BATCH 4
#define SEQ   1024
#define DIM   1152
#define HEADS 16
#define HDIM  72
#define ROWS  (BATCH*SEQ)          // 4096
#define QKVN  (3*DIM)              // 3456
#define TOTAL_ELEMS 4718592.0f     // B*H*N*hd for loss mean

// Scratch (static device allocation — allowed)
__device__ __align__(16) float g_qkv [(size_t)ROWS * QKVN];   // 56.6 MB, (B*N, 3456)
__device__ __align__(16) float g_xout[(size_t)ROWS * DIM];    // 18.9 MB, (B*N, 1152) = (B,N,H,hd)

// ---------------------------------------------------------------------------
// GEMM: C[m,n] = sum_k A[m,k] * W[n,k] + bias[n]
// BM=128, BN=64, BK=16, 256 threads, 8x4 micro-tile
// ---------------------------------------------------------------------------
__global__ __launch_bounds__(256)
void gemm_bias_kernel(const float* __restrict__ A, const float* __restrict__ W,
                      const float* __restrict__ bias, float* __restrict__ C,
                      int M, int N, int K)
{
    __shared__ __align__(16) float As[16][128];
    __shared__ __align__(16) float Bs[16][64];

    const int tid = threadIdx.x;
    const int tx = tid & 15;         // 0..15 -> n
    const int ty = tid >> 4;         // 0..15 -> m
    const int m0 = blockIdx.y * 128;
    const int n0 = blockIdx.x * 64;

    float acc[8][4];
#pragma unroll
    for (int i = 0; i < 8; i++)
#pragma unroll
        for (int j = 0; j < 4; j++) acc[i][j] = 0.f;

    const int ktiles = K >> 4;
    for (int kt = 0; kt < ktiles; kt++) {
        const int k0 = kt << 4;
        // Load A tile: 128 rows x 16 cols = 512 float4
#pragma unroll
        for (int r = 0; r < 2; r++) {
            int e = tid + r * 256;
            int row = e >> 2;
            int kc  = (e & 3) << 2;
            float4 va = *(const float4*)&A[(size_t)(m0 + row) * K + k0 + kc];
            As[kc + 0][row] = va.x; As[kc + 1][row] = va.y;
            As[kc + 2][row] = va.z; As[kc + 3][row] = va.w;
        }
        // Load B tile: 64 rows x 16 cols = 256 float4
        {
            int row = tid >> 2;
            int kc  = (tid & 3) << 2;
            float4 vb = *(const float4*)&W[(size_t)(n0 + row) * K + k0 + kc];
            Bs[kc + 0][row] = vb.x; Bs[kc + 1][row] = vb.y;
            Bs[kc + 2][row] = vb.z; Bs[kc + 3][row] = vb.w;
        }
        __syncthreads();
#pragma unroll
        for (int k = 0; k < 16; k++) {
            float4 a0 = *(const float4*)&As[k][ty * 8];
            float4 a1 = *(const float4*)&As[k][ty * 8 + 4];
            float4 b  = *(const float4*)&Bs[k][tx * 4];
            float am[8] = {a0.x, a0.y, a0.z, a0.w, a1.x, a1.y, a1.z, a1.w};
            float bn[4] = {b.x, b.y, b.z, b.w};
#pragma unroll
            for (int i = 0; i < 8; i++)
#pragma unroll
                for (int j = 0; j < 4; j++) acc[i][j] += am[i] * bn[j];
        }
        __syncthreads();
    }

    const float4 bv = *(const float4*)&bias[n0 + tx * 4];
#pragma unroll
    for (int i = 0; i < 8; i++) {
        float4 o;
        o.x = acc[i][0] + bv.x; o.y = acc[i][1] + bv.y;
        o.z = acc[i][2] + bv.z; o.w = acc[i][3] + bv.w;
        *(float4*)&C[(size_t)(m0 + ty * 8 + i) * N + n0 + tx * 4] = o;
    }
}

// ---------------------------------------------------------------------------
// Fused dual attention + distill loss.
// grid: (16 q-tiles, 64 bh). block: 256 threads = 8 warps.
// Each warp owns 8 queries; 4 lanes per query, each lane owns 18 dims.
// Pass 0: own K/V (from g_qkv) -> writes g_xout. Pass 1: encoder K/V -> loss.
// ---------------------------------------------------------------------------
__global__ __launch_bounds__(256)
void attn_kernel(const float* __restrict__ enc_k, const float* __restrict__ enc_v,
                 float* __restrict__ loss_out)
{
    __shared__ __align__(16) float Ks[64][72];
    __shared__ __align__(16) float Vs[64][72];

    const int tid  = threadIdx.x;
    const int lane = tid & 31;
    const int warp = tid >> 5;
    const int sub  = lane & 3;                 // 4 lanes per query
    const int qloc = warp * 8 + (lane >> 2);   // 0..63
    const int bh = blockIdx.y;
    const int b  = bh >> 4;
    const int h  = bh & 15;
    const int n  = blockIdx.x * 64 + qloc;
    const float scale = rsqrtf((float)HDIM);

    // Load this lane's 18 Q dims (pre-scaled)
    float2 qr[9];
    {
        const float* qs = g_qkv + ((size_t)(b * SEQ + n)) * QKVN + h * HDIM + sub * 18;
#pragma unroll
        for (int j = 0; j < 9; j++) {
            float2 v = ((const float2*)qs)[j];
            qr[j].x = v.x * scale; qr[j].y = v.y * scale;
        }
    }

    float xo[18];           // pass-0 output, kept for loss
    float lsum = 0.f;

    for (int p = 0; p < 2; p++) {
        float m = -1e30f, l = 0.f;
        float2 O[9];
#pragma unroll
        for (int j = 0; j < 9; j++) O[j] = make_float2(0.f, 0.f);

        for (int kt = 0; kt < 16; kt++) {
            float2* ksm = (float2*)&Ks[0][0];
            float2* vsm = (float2*)&Vs[0][0];
            if (p == 0) {
#pragma unroll
                for (int r = 0; r < 9; r++) {
                    int e = tid + r * 256;            // 0..2303 (float2 units)
                    int key = e / 36;
                    int dp  = e - key * 36;
                    size_t base = ((size_t)(b * SEQ + kt * 64 + key)) * QKVN + h * HDIM + dp * 2;
                    ksm[e] = *(const float2*)(g_qkv + base + DIM);
                    vsm[e] = *(const float2*)(g_qkv + base + 2 * DIM);
                }
            } else {
                const float2* kst = (const float2*)(enc_k + ((size_t)bh * SEQ + kt * 64) * HDIM);
                const float2* vst = (const float2*)(enc_v + ((size_t)bh * SEQ + kt * 64) * HDIM);
#pragma unroll
                for (int r = 0; r < 9; r++) {
                    int e = tid + r * 256;
                    ksm[e] = kst[e];
                    vsm[e] = vst[e];
                }
            }
            __syncthreads();

            // Scores for 64 keys; each lane keeps 16 of them (static indices)
            float sc[16];
            float tmax = -1e30f;
#pragma unroll
            for (int i = 0; i < 16; i++) {
#pragma unroll
                for (int u = 0; u < 4; u++) {
                    const int kk = i * 4 + u;
                    const float2* kr = (const float2*)&Ks[kk][sub * 18];
                    float s = 0.f;
#pragma unroll
                    for (int j = 0; j < 9; j++) {
                        float2 kv = kr[j];
                        s += qr[j].x * kv.x + qr[j].y * kv.y;
                    }
                    s += __shfl_xor_sync(0xffffffffu, s, 1);
                    s += __shfl_xor_sync(0xffffffffu, s, 2);   // full dot on all 4 lanes
                    if (u == sub) sc[i] = s;
                    tmax = fmaxf(tmax, s);
                }
            }
            // Online softmax update
            float nm = fmaxf(m, tmax);
            float corr = __expf(m - nm);
            l *= corr;
#pragma unroll
            for (int j = 0; j < 9; j++) { O[j].x *= corr; O[j].y *= corr; }
            float ps = 0.f;
#pragma unroll
            for (int i = 0; i < 16; i++) { sc[i] = __expf(sc[i] - nm); ps += sc[i]; }
            ps += __shfl_xor_sync(0xffffffffu, ps, 1);
            ps += __shfl_xor_sync(0xffffffffu, ps, 2);
            l += ps; m = nm;

            // O += P @ V
#pragma unroll
            for (int i = 0; i < 16; i++) {
#pragma unroll
                for (int u = 0; u < 4; u++) {
                    const int kk = i * 4 + u;
                    float pv = __shfl_sync(0xffffffffu, sc[i], (lane & ~3) | u);
                    const float2* vr = (const float2*)&Vs[kk][sub * 18];
#pragma unroll
                    for (int j = 0; j < 9; j++) {
                        float2 vv = vr[j];
                        O[j].x += pv * vv.x; O[j].y += pv * vv.y;
                    }
                }
            }
            __syncthreads();
        }

        const float inv_l = 1.0f / l;
        if (p == 0) {
            float* dst = g_xout + ((size_t)(b * SEQ + n)) * DIM + h * HDIM + sub * 18;
#pragma unroll
            for (int j = 0; j < 9; j++) {
                xo[2 * j]     = O[j].x * inv_l;
                xo[2 * j + 1] = O[j].y * inv_l;
                ((float2*)dst)[j] = make_float2(xo[2 * j], xo[2 * j + 1]);
            }
        } else {
#pragma unroll
            for (int j = 0; j < 9; j++) {
                float d0 = xo[2 * j]     - O[j].x * inv_l;
                float d1 = xo[2 * j + 1] - O[j].y * inv_l;
                lsum += d0 * d0 + d1 * d1;
            }
        }
    }

    // Loss: mean over all elements; warp-reduce then one atomic per warp
    lsum *= (1.0f / TOTAL_ELEMS);
#pragma unroll
    for (int o = 16; o > 0; o >>= 1)
        lsum += __shfl_down_sync(0xffffffffu, lsum, o);
    if (lane == 0) atomicAdd(loss_out, lsum);
}

// ---------------------------------------------------------------------------
extern "C" void kernel_launch(void* const* d_in, const int* in_sizes, int n_in,
                              void* d_out, int out_size)
{
    const float* x      = (const float*)d_in[0];
    const float* enc_k  = (const float*)d_in[1];
    const float* enc_v  = (const float*)d_in[2];
    const float* qkv_w  = (const float*)d_in[3];
    const float* qkv_b  = (const float*)d_in[4];
    const float* proj_w = (const float*)d_in[5];
    const float* proj_b = (const float*)d_in[6];
    float* out = (float*)d_out;
    float* loss_ptr = out + (out_size - 1);

    float* qkv_ptr = nullptr;
    float* xout_ptr = nullptr;
    cudaGetSymbolAddress((void**)&qkv_ptr,  g_qkv);
    cudaGetSymbolAddress((void**)&xout_ptr, g_xout);

    cudaMemsetAsync(loss_ptr, 0, sizeof(float));

    // 1) QKV GEMM: (4096,1152) @ (3456,1152)^T + b -> g_qkv (4096,3456)
    gemm_bias_kernel<<<dim3(QKVN / 64, ROWS / 128), 256>>>(
        x, qkv_w, qkv_b, qkv_ptr, ROWS, QKVN, DIM);

    // 2) Dual attention + loss -> g_xout (4096,1152), loss scalar
    attn_kernel<<<dim3(SEQ / 64, BATCH * HEADS), 256>>>(enc_k, enc_v, loss_ptr);

    // 3) Proj GEMM: (4096,1152) @ (1152,1152)^T + b -> out
    gemm_bias_kernel<<<dim3(DIM / 64, ROWS / 128), 256>>>(
        xout_ptr, proj_w, proj_b, out, ROWS, DIM, DIM);
}